// round 12
// baseline (speedup 1.0000x reference)
#include <cuda_runtime.h>
#include <cstdint>

#define N_TOKENS (16*8192)
#define HD       256
#define NEXP     32
#define BATCH    16
#define SEQ      8192
#define TPB      256
#define WARPS    8
#define TOK_PER_TILE 32
#define NTILES   (N_TOKENS/TOK_PER_TILE)   // 4096 warp-tiles
#define NBLK     296                       // 2 x 148 SMs
#define NH       (HD/16)                   // 16 h-groups (16 k each)
#define NSTAGE   3
#define STAGE_B  2048                      // 32 rows x 16 floats
// dyn smem: B table 64 KB + A rings 8*3*2 KB = 112 KB
#define BT_BYTES (32*4*32*4*4)
#define SMEM_DYN (BT_BYTES + WARPS*NSTAGE*STAGE_B)

__device__ float g_ssum[BATCH*NEXP];
__device__ int   g_cnt [BATCH*NEXP];
__device__ unsigned g_done;

__device__ __forceinline__ uint32_t tf32_hi(float x) {
    uint32_t r; asm("cvt.rna.tf32.f32 %0, %1;" : "=r"(r) : "f"(x)); return r;
}
__device__ __forceinline__ void mma_tf32(float* c,
        uint32_t a0, uint32_t a1, uint32_t a2, uint32_t a3,
        uint32_t b0, uint32_t b1) {
    asm volatile(
        "mma.sync.aligned.m16n8k8.row.col.f32.tf32.tf32.f32 "
        "{%0,%1,%2,%3}, {%4,%5,%6,%7}, {%8,%9}, {%0,%1,%2,%3};"
        : "+f"(c[0]), "+f"(c[1]), "+f"(c[2]), "+f"(c[3])
        : "r"(a0), "r"(a1), "r"(a2), "r"(a3), "r"(b0), "r"(b1));
}
__device__ __forceinline__ void cp_async16(uint32_t dst, const void* src) {
    asm volatile("cp.async.cg.shared.global [%0], [%1], 16;\n" :: "r"(dst), "l"(src));
}
__device__ __forceinline__ void cp_commit() {
    asm volatile("cp.async.commit_group;\n");
}
template<int N> __device__ __forceinline__ void cp_wait() {
    asm volatile("cp.async.wait_group %0;\n" :: "n"(N));
}

extern __shared__ uint32_t smem_dyn[];

__global__ void __launch_bounds__(TPB, 2)
gate_kernel(const float* __restrict__ hs, const float* __restrict__ w,
            float* __restrict__ out)
{
    __shared__ float s_aux[2][NEXP];
    __shared__ int   s_cnt[2][NEXP];
    __shared__ int   s_last;

    uint32_t* Btab = smem_dyn;
    char* Aring = (char*)smem_dyn + BT_BYTES;

    const int tid  = threadIdx.x;
    const int lane = tid & 31;
    const int warp = tid >> 5;
    const int lq   = lane & 3;
    const int lr   = lane >> 2;

    const int t_start = (int)(((long long)blockIdx.x * NTILES) / NBLK);
    const int t_end   = (int)(((long long)(blockIdx.x + 1) * NTILES) / NBLK);
    const int b_base  = t_start >> 8;

    // ---- build B fragment table (hi/lo tf32; same permutation as R11) ----
    #pragma unroll 4
    for (int it = 0; it < NEXP; it++) {
        float v = w[it*HD + tid];
        uint32_t hi = tf32_hi(v);
        float lo = v - __uint_as_float(hi);
        int k = tid;
        int h = k >> 4, j = k & 15, q = j >> 2, rr = j & 3;
        int ks = 2*h + (rr >> 1), r = rr & 1;
        int nt = it >> 3, t = (it & 7)*4 + q;
        int idx = ((ks*4 + nt)*32 + t)*4;
        Btab[idx + r]     = hi;
        Btab[idx + 2 + r] = __float_as_uint(lo);
    }
    if (tid < 2*NEXP) { s_aux[tid>>5][tid&31] = 0.0f; s_cnt[tid>>5][tid&31] = 0; }
    __syncthreads();

    // this warp's A ring (3 stages x 2 KB), plus this lane's cp.async row/col
    char* Awarp = Aring + warp * (NSTAGE*STAGE_B);
    const uint32_t Abase = (uint32_t)__cvta_generic_to_shared(Awarp);
    const int cp_row = lane >> 2;        // 0..7 (x4 iterations -> 32 rows)
    const int cp_gr  = lane & 3;         // granule within 64B row

    for (int tile = t_start + warp; tile < t_end; tile += WARPS) {
        const int tb = tile * TOK_PER_TILE;
        const int bi = (tile >> 8) - b_base;
        const float* xbase = hs + (size_t)tb * HD;

        // ---- prologue: stage h-groups 0..2 ----
        #pragma unroll
        for (int p = 0; p < NSTAGE; p++) {
            uint32_t dst = Abase + p*STAGE_B;
            #pragma unroll
            for (int it = 0; it < 4; it++) {
                int row = it*8 + cp_row;
                cp_async16(dst + row*64 + cp_gr*16,
                           xbase + (size_t)row*HD + p*16 + cp_gr*4);
            }
            cp_commit();
        }

        float acc[2][4][4];
        #pragma unroll
        for (int mt = 0; mt < 2; mt++)
            #pragma unroll
            for (int nt = 0; nt < 4; nt++)
                #pragma unroll
                for (int i = 0; i < 4; i++) acc[mt][nt][i] = 0.0f;

        #pragma unroll
        for (int h = 0; h < NH; h++) {
            cp_wait<2>();                            // stage h resident
            const char* st = Awarp + (h % NSTAGE)*STAGE_B;

            // fragment rows from smem (conflict-free LDS.128)
            float4 cur[4];
            #pragma unroll
            for (int i = 0; i < 4; i++)
                cur[i] = *(const float4*)(st + (i*8 + lr)*64 + lq*16);

            // refill the slot we just consumed with h-group h+3
            if (h + NSTAGE < NH) {
                uint32_t dst = Abase + (h % NSTAGE)*STAGE_B;
                #pragma unroll
                for (int it = 0; it < 4; it++) {
                    int row = it*8 + cp_row;
                    cp_async16(dst + row*64 + cp_gr*16,
                               xbase + (size_t)row*HD + (h+NSTAGE)*16 + cp_gr*4);
                }
            }
            cp_commit();                             // commit (possibly empty) group

            #pragma unroll
            for (int s01 = 0; s01 < 2; s01++) {
                uint32_t ah[4][2], al[4][2];
                #pragma unroll
                for (int i = 0; i < 4; i++) {
                    float f0 = s01 ? cur[i].z : cur[i].x;
                    float f1 = s01 ? cur[i].w : cur[i].y;
                    ah[i][0] = tf32_hi(f0);
                    ah[i][1] = tf32_hi(f1);
                    al[i][0] = __float_as_uint(f0 - __uint_as_float(ah[i][0]));
                    al[i][1] = __float_as_uint(f1 - __uint_as_float(ah[i][1]));
                }
                const uint32_t* bt = &Btab[((8*h + s01*4)*32 + lane)*4];
                #pragma unroll
                for (int nt = 0; nt < 4; nt++) {
                    uint4 bb = *(const uint4*)(bt + nt*128);
                    #pragma unroll
                    for (int mt = 0; mt < 2; mt++) {
                        const int r0 = mt*2, r1 = mt*2 + 1;
                        mma_tf32(acc[mt][nt], ah[r0][0], ah[r1][0], ah[r0][1], ah[r1][1], bb.x, bb.y);
                        mma_tf32(acc[mt][nt], ah[r0][0], ah[r1][0], ah[r0][1], ah[r1][1], bb.z, bb.w);
                        mma_tf32(acc[mt][nt], al[r0][0], al[r1][0], al[r0][1], al[r1][1], bb.x, bb.y);
                    }
                }
            }
        }
        cp_wait<0>();                                // drain before next tile reuses ring

        // ---- epilogue: token row (mt*16 + half*8 + lr), logits across quad ----
        float aux8[8];
        #pragma unroll
        for (int i = 0; i < 8; i++) aux8[i] = 0.0f;

        #pragma unroll
        for (int mt = 0; mt < 2; mt++) {
            #pragma unroll
            for (int half = 0; half < 2; half++) {
                float lg[8];
                #pragma unroll
                for (int nt = 0; nt < 4; nt++) {
                    lg[nt*2]   = acc[mt][nt][half*2];
                    lg[nt*2+1] = acc[mt][nt][half*2+1];
                }
                float m = lg[0]; int a = lq*2;
                #pragma unroll
                for (int i = 1; i < 8; i++) {
                    int e = (i>>1)*8 + lq*2 + (i&1);
                    if (lg[i] > m) { m = lg[i]; a = e; }
                }
                #pragma unroll
                for (int d = 1; d <= 2; d <<= 1) {
                    float om = __shfl_xor_sync(0xffffffffu, m, d);
                    int   oa = __shfl_xor_sync(0xffffffffu, a, d);
                    if (om > m || (om == m && oa < a)) { m = om; a = oa; }
                }
                float ex[8]; float s = 0.0f;
                #pragma unroll
                for (int i = 0; i < 8; i++) { ex[i] = __expf(lg[i] - m); s += ex[i]; }
                #pragma unroll
                for (int d = 1; d <= 2; d <<= 1) s += __shfl_xor_sync(0xffffffffu, s, d);
                float inv = 1.0f / s;
                #pragma unroll
                for (int i = 0; i < 8; i++) aux8[i] += ex[i] * inv;
                if (lq == 0) {
                    int gidx = tb + mt*16 + half*8 + lr;
                    out[gidx]            = (float)a;
                    out[N_TOKENS + gidx] = inv;
                    atomicAdd(&s_cnt[bi][a], 1);
                }
            }
        }

        #pragma unroll
        for (int i = 0; i < 8; i++) {
            float v = aux8[i];
            #pragma unroll
            for (int d = 4; d <= 16; d <<= 1) v += __shfl_xor_sync(0xffffffffu, v, d);
            if (lane < 4) atomicAdd(&s_aux[bi][(i>>1)*8 + lane*2 + (i&1)], v);
        }
    }
    __syncthreads();

    if (tid < 2*NEXP) {
        int r = tid >> 5, e = tid & 31;
        int br = b_base + r;
        if (br < BATCH) {
            atomicAdd(&g_ssum[br*NEXP + e], s_aux[r][e]);
            atomicAdd(&g_cnt [br*NEXP + e], s_cnt[r][e]);
        }
    }

    // ---- last block: finalize aux loss, reset globals ----
    if (tid == 0) {
        __threadfence();
        unsigned ticket = atomicAdd(&g_done, 1u);
        s_last = (ticket == (unsigned)(gridDim.x - 1));
    }
    __syncthreads();
    if (s_last) {
        __threadfence();
        __shared__ float red[TPB];
        float term = 0.0f;
        #pragma unroll
        for (int i = tid; i < BATCH*NEXP; i += TPB)
            term += ((float)g_cnt[i] * (1.0f/256.0f)) * (g_ssum[i] * (1.0f/(float)SEQ));
        red[tid] = term;
        __syncthreads();
        #pragma unroll
        for (int s2 = TPB/2; s2 > 0; s2 >>= 1) {
            if (tid < s2) red[tid] += red[tid + s2];
            __syncthreads();
        }
        if (tid == 0) out[2*N_TOKENS] = red[0] * (0.001f / (float)BATCH);
        #pragma unroll
        for (int i = tid; i < BATCH*NEXP; i += TPB) { g_ssum[i] = 0.0f; g_cnt[i] = 0; }
        if (tid == 0) g_done = 0u;
    }
}

extern "C" void kernel_launch(void* const* d_in, const int* in_sizes, int n_in,
                              void* d_out, int out_size) {
    const float* hs = (const float*)d_in[0];
    const float* w  = (const float*)d_in[1];
    float* out = (float*)d_out;
    cudaFuncSetAttribute(gate_kernel, cudaFuncAttributeMaxDynamicSharedMemorySize, SMEM_DYN);
    gate_kernel<<<NBLK, TPB, SMEM_DYN>>>(hs, w, out);
}